// round 14
// baseline (speedup 1.0000x reference)
#include <cuda_runtime.h>
#include <cuda_fp16.h>
#include <cstdint>
#include <cstddef>

// ---------------- Problem constants ----------------
#define IMG   224
#define PATCH 16
#define EMB   768
#define DEPTH 12
#define NHEAD 12
#define HD    64
#define FF    3072
#define NCLS  1000
#define BATCH 32
#define NP    196
#define NTOK  197
#define ROWS  (BATCH * NTOK) // 6304
#define PROWS (BATCH * NP)   // 6272
#define EPS   1e-5f
#define QS    2304           // fused qkv row stride
#define NSPLIT 4             // split-K factor for O-proj / FF2

// weight layout (per layer, element offsets). Q,K,V contiguous -> fused QKV.
#define OFF_Q   0
#define OFF_K   589824
#define OFF_V   1179648
#define OFF_O   1769472
#define OFF_W1  2359296
#define OFF_W2  4718592
#define LSTRIDE 7077888
#define WTOTAL  (LSTRIDE * DEPTH)

// ---------------- Scratch ----------------
__device__ float g_h  [ROWS * EMB];             // trunk fp32
__device__ float g_x  [ROWS * EMB];             // post-LN1 fp32
__device__ float g_t  [NSPLIT * ROWS * EMB];    // split-K partial buffers
__device__ float g_cls[BATCH * EMB];
__device__ __half g_qkv[ROWS * QS];             // fused qkv fp16
__device__ __half g_hh [ROWS * EMB];
__device__ __half g_xh [ROWS * EMB];
__device__ __half g_th [ROWS * EMB];
__device__ __half g_fh [ROWS * FF];
__device__ __half g_imh[PROWS * EMB];
__device__ __half g_w  [WTOTAL];                // weights fp16, [N,K]
__device__ __half g_cw [EMB * EMB];

// ---------------- helpers ----------------
__device__ __forceinline__ uint32_t smem_u32(const void* p) {
    uint32_t a;
    asm("{ .reg .u64 t; cvta.to.shared.u64 t, %1; cvt.u32.u64 %0, t; }"
        : "=r"(a) : "l"(p));
    return a;
}
__device__ __forceinline__ void ldm_x4(uint32_t (&r)[4], uint32_t addr) {
    asm volatile("ldmatrix.sync.aligned.m8n8.x4.shared.b16 {%0,%1,%2,%3}, [%4];"
                 : "=r"(r[0]), "=r"(r[1]), "=r"(r[2]), "=r"(r[3]) : "r"(addr));
}
__device__ __forceinline__ void ldm_x4_trans(uint32_t (&r)[4], uint32_t addr) {
    asm volatile("ldmatrix.sync.aligned.m8n8.x4.trans.shared.b16 {%0,%1,%2,%3}, [%4];"
                 : "=r"(r[0]), "=r"(r[1]), "=r"(r[2]), "=r"(r[3]) : "r"(addr));
}
__device__ __forceinline__ void mma_f16(float (&d)[4], const uint32_t (&a)[4],
                                        const uint32_t (&b)[2]) {
    asm volatile("mma.sync.aligned.m16n8k16.row.col.f32.f16.f16.f32 "
                 "{%0,%1,%2,%3}, {%4,%5,%6,%7}, {%8,%9}, {%0,%1,%2,%3};"
                 : "+f"(d[0]), "+f"(d[1]), "+f"(d[2]), "+f"(d[3])
                 : "r"(a[0]), "r"(a[1]), "r"(a[2]), "r"(a[3]),
                   "r"(b[0]), "r"(b[1]));
}
__device__ __forceinline__ uint32_t pack_h2(float x, float y) {
    __half2 h = __floats2half2_rn(x, y);
    return *reinterpret_cast<uint32_t*>(&h);
}

// ---------------- weight prep: transpose [K,N] -> [N,K], fp16 ---------------
__global__ void transpose_half_batch(const float* __restrict__ W,
                                     __half* __restrict__ out,
                                     int K, int N,
                                     size_t w_lstride, size_t o_lstride)
{
    __shared__ float t[32][33];
    const int layer = blockIdx.z;
    W   += (size_t)layer * w_lstride;
    out += (size_t)layer * o_lstride;
    int nb = blockIdx.x * 32, kb = blockIdx.y * 32;
    int tx = threadIdx.x, ty = threadIdx.y;
    #pragma unroll
    for (int j = ty; j < 32; j += 8)
        t[j][tx] = W[(size_t)(kb + j) * N + nb + tx];
    __syncthreads();
    #pragma unroll
    for (int j = ty; j < 32; j += 8)
        out[(size_t)(nb + j) * K + kb + tx] = __float2half_rn(t[tx][j]);
}

__global__ void tohalf_only(const float* __restrict__ W,
                            __half* __restrict__ out, int n)
{
    int i = blockIdx.x * blockDim.x + threadIdx.x;
    if (i < n) out[i] = __float2half_rn(W[i]);
}

// ---------------- pipelined HMMA GEMM (single-pass fp16, fp32 accum) --------
#define BM 128
#define BN 128
#define BK 64
#define ROWB 144                    // 64*2 + 16 pad bytes per smem row
#define ARR_B (128 * ROWB)          // 18432
#define STAGE_B (2 * ARR_B)         // 36864
#define GEMM_SMEM (3 * STAGE_B)     // 110592 (3-stage)

__global__ __launch_bounds__(256, 2)
void gemm_hmma(const __half* __restrict__ A,
               const __half* __restrict__ B,
               const float* __restrict__ bias,
               float* __restrict__ Cf,
               __half* __restrict__ Ch,
               int M, int N, int Kspan, int ldK, int do_relu)
{
    extern __shared__ __align__(16) unsigned char dsm[];
    const uint32_t smb = smem_u32(dsm);
    const int tid  = threadIdx.x;
    const int lane = tid & 31;
    const int wid  = tid >> 5;
    const int wm   = wid & 1;
    const int wn   = wid >> 1;
    const int row0 = blockIdx.y * BM;
    const int col0 = blockIdx.x * BN;
    const int kz   = blockIdx.z;

    const __half* Ab = A + (size_t)kz * Kspan;
    const __half* Bb = B + (size_t)kz * Kspan;
    if (Cf) Cf += (size_t)kz * M * N;

    float acc[4][4][4] = {};

    auto load_stage = [&](int s, int kt) {
        #pragma unroll
        for (int l = 0; l < 8; l++) {
            int idx = tid + l * 256;
            int arr = idx >> 10;
            int w   = idx & 1023;
            int r   = w >> 3;
            int q   = w & 7;
            int row = (arr ? col0 : row0) + r;
            const __half* src = (arr ? Bb : Ab) + (size_t)row * ldK + kt + q * 8;
            int bytes = (!arr && row >= M) ? 0 : 16;
            uint32_t dst = smb + (uint32_t)s * STAGE_B + (uint32_t)arr * ARR_B
                         + (uint32_t)r * ROWB + (uint32_t)q * 16u;
            asm volatile("cp.async.cg.shared.global [%0], [%1], 16, %2;"
                         :: "r"(dst), "l"(src), "r"(bytes) : "memory");
        }
        asm volatile("cp.async.commit_group;" ::: "memory");
    };

    auto compute_stage = [&](int s) {
        const uint32_t uA = smb + (uint32_t)s * STAGE_B;
        const uint32_t uB = uA + ARR_B;
        #pragma unroll
        for (int kk = 0; kk < 4; kk++) {
            const uint32_t kcb = (kk * 16 + ((lane >> 4) << 3)) * 2;
            uint32_t af[4][4];
            uint32_t bf[4][2];
            #pragma unroll
            for (int mi = 0; mi < 4; mi++) {
                uint32_t off = (uint32_t)(wm * 64 + mi * 16 + (lane & 15)) * ROWB + kcb;
                ldm_x4(af[mi], uA + off);
            }
            #pragma unroll
            for (int g = 0; g < 2; g++) {
                uint32_t off = (uint32_t)(wn * 32 + g * 16 + (lane & 15)) * ROWB + kcb;
                uint32_t tb[4];
                ldm_x4(tb, uB + off);
                bf[g*2+0][0] = tb[0]; bf[g*2+0][1] = tb[2];
                bf[g*2+1][0] = tb[1]; bf[g*2+1][1] = tb[3];
            }
            #pragma unroll
            for (int mi = 0; mi < 4; mi++)
                #pragma unroll
                for (int n = 0; n < 4; n++)
                    mma_f16(acc[mi][n], af[mi], bf[n]);
        }
    };

    const int nk = Kspan / BK;          // >= 3 for all launched shapes
    load_stage(0, 0);
    load_stage(1, BK);
    for (int i = 0; i < nk; i++) {
        if (i == nk - 1)
            asm volatile("cp.async.wait_group 0;" ::: "memory");
        else
            asm volatile("cp.async.wait_group 1;" ::: "memory");
        __syncthreads();    // group i visible; all threads done computing stage (i-1)
        if (i + 2 < nk)
            load_stage((i + 2) % 3, (i + 2) * BK);
        compute_stage(i % 3);
    }

    // ---- epilogue ----
    const bool hb = (bias != nullptr);
    #pragma unroll
    for (int mi = 0; mi < 4; mi++) {
        #pragma unroll
        for (int n = 0; n < 4; n++) {
            int gc = col0 + wn * 32 + n * 8 + (lane & 3) * 2;
            float bx = 0.f, by = 0.f;
            if (hb) { bx = bias[gc]; by = bias[gc + 1]; }
            #pragma unroll
            for (int h = 0; h < 2; h++) {
                int gr = row0 + wm * 64 + mi * 16 + (lane >> 2) + h * 8;
                if (gr >= M) continue;
                float ox = acc[mi][n][h * 2 + 0] + bx;
                float oy = acc[mi][n][h * 2 + 1] + by;
                if (do_relu) { ox = fmaxf(ox, 0.f); oy = fmaxf(oy, 0.f); }
                size_t o = (size_t)gr * N + gc;
                if (Cf)
                    *reinterpret_cast<float2*>(&Cf[o]) = make_float2(ox, oy);
                if (Ch)
                    *reinterpret_cast<uint32_t*>(&Ch[o]) = pack_h2(ox, oy);
            }
        }
    }
}

// ---------------- im2col (emits fp16) ---------------------------------------
__global__ void im2col_kernel(const float* __restrict__ x,
                              __half* __restrict__ ho)
{
    int idx = blockIdx.x * blockDim.x + threadIdx.x;
    if (idx >= PROWS * EMB) return;
    int row = idx / EMB;
    int k   = idx % EMB;
    int b   = row / NP;
    int p   = row % NP;
    int py  = p / 14, px = p % 14;
    int c   = k / 256;
    int r2  = k % 256;
    int ph  = r2 / PATCH, pw = r2 % PATCH;
    float v = x[(((size_t)b * 3 + c) * IMG + (py * PATCH + ph)) * IMG
                + (px * PATCH + pw)];
    ho[idx] = __float2half_rn(v);
}

__global__ void embed_kernel(const float* __restrict__ patch,
                             const float* __restrict__ cls_tok,
                             const float* __restrict__ pos,
                             float* __restrict__ h,
                             __half* __restrict__ hh)
{
    int idx = blockIdx.x * blockDim.x + threadIdx.x;
    if (idx >= ROWS * EMB) return;
    int row = idx / EMB;
    int e   = idx % EMB;
    int b   = row / NTOK;
    int n   = row % NTOK;
    float base = (n == 0) ? cls_tok[e]
                          : patch[((size_t)b * NP + (n - 1)) * EMB + e];
    float v = base + pos[n * EMB + e];
    h[idx]  = v;
    hh[idx] = __float2half_rn(v);
}

// ---------------- tensor-core fused attention --------------------------------
#define AT_QSTR 72
#define AT_KSTR 72
#define AT_ASTR 232
#define AT_Q_OFF   0
#define AT_KV_OFF  9216          // 64*72*2
#define AT_A_OFF   41472         // 9216 + 224*72*2
#define AT_RED_OFF 71168         // 41472 + 64*232*2
#define ATT_SMEM   72192         // + 256*4

__global__ __launch_bounds__(256, 2)
void attn_tc(const __half* __restrict__ qkv, __half* __restrict__ th)
{
    extern __shared__ __align__(16) char smc[];
    __half* Qh = reinterpret_cast<__half*>(smc + AT_Q_OFF);
    __half* Kh = reinterpret_cast<__half*>(smc + AT_KV_OFF);   // K, then V
    __half* Ah = reinterpret_cast<__half*>(smc + AT_A_OFF);
    float* redM = reinterpret_cast<float*>(smc + AT_RED_OFF);  // [2][64]
    float* redS = redM + 128;                                  // [2][64]

    const int bh = blockIdx.y;
    const int b  = bh / NHEAD;
    const int hh = bh % NHEAD;
    const int q0 = blockIdx.x * 64;
    const float scale = 0.036084391824f;   // 1/sqrt(768)

    const int tid  = threadIdx.x;
    const int lane = tid & 31;
    const int wid  = tid >> 5;
    const int wm   = wid & 3;
    const int wn   = wid >> 2;

    const __half* Qb = qkv + (size_t)b * NTOK * QS + hh * HD;
    const __half* Kb = Qb + 768;
    const __half* Vb = Qb + 1536;

    const uint32_t uQ = smem_u32(Qh);
    const uint32_t uK = smem_u32(Kh);
    const uint32_t uA = smem_u32(Ah);

    // ---- load Q (64 x 64) ----
    #pragma unroll
    for (int l = 0; l < 4; l++) {
        int idx = tid + l * 256;
        int r   = idx >> 4;
        int c4  = (idx & 15) << 2;
        uint2 v = make_uint2(0u, 0u);
        if (q0 + r < NTOK)
            v = *reinterpret_cast<const uint2*>(&Qb[(size_t)(q0 + r) * QS + c4]);
        *reinterpret_cast<uint32_t*>(&Qh[r * AT_QSTR + c4])     = v.x;
        *reinterpret_cast<uint32_t*>(&Qh[r * AT_QSTR + c4 + 2]) = v.y;
    }
    // ---- load K (224 x 64, zero-padded past NTOK) ----
    #pragma unroll
    for (int l = 0; l < 14; l++) {
        int idx = tid + l * 256;
        int r   = idx >> 4;
        int c4  = (idx & 15) << 2;
        uint2 v = make_uint2(0u, 0u);
        if (r < NTOK)
            v = *reinterpret_cast<const uint2*>(&Kb[(size_t)r * QS + c4]);
        *reinterpret_cast<uint32_t*>(&Kh[r * AT_KSTR + c4])     = v.x;
        *reinterpret_cast<uint32_t*>(&Kh[r * AT_KSTR + c4 + 2]) = v.y;
    }
    __syncthreads();

    // ---- phase 1: scores via mma ----
    float acc[14][4];
    #pragma unroll
    for (int t = 0; t < 14; t++)
        #pragma unroll
        for (int j = 0; j < 4; j++) acc[t][j] = 0.f;

    #pragma unroll
    for (int ks = 0; ks < 4; ks++) {
        const uint32_t kcb = (ks * 16 + ((lane >> 4) << 3)) * 2;
        uint32_t af[4];
        ldm_x4(af, uQ + (uint32_t)(wm * 16 + (lane & 15)) * (AT_QSTR * 2) + kcb);
        #pragma unroll
        for (int g = 0; g < 7; g++) {
            uint32_t tb[4];
            ldm_x4(tb, uK + (uint32_t)(wn * 112 + g * 16 + (lane & 15)) * (AT_KSTR * 2) + kcb);
            uint32_t b0[2] = {tb[0], tb[2]};
            uint32_t b1[2] = {tb[1], tb[3]};
            mma_f16(acc[g * 2 + 0], af, b0);
            mma_f16(acc[g * 2 + 1], af, b1);
        }
    }

    // ---- register softmax ----
    const int row0 = wm * 16 + (lane >> 2);
    const int cb   = wn * 112 + (lane & 3) * 2;
    #pragma unroll
    for (int t = 0; t < 14; t++) {
        #pragma unroll
        for (int j = 0; j < 4; j++) {
            int gc = cb + t * 8 + (j & 1);
            float v = acc[t][j] * scale;
            acc[t][j] = (gc < NTOK) ? v : -1e30f;
        }
    }
    float m0 = -1e30f, m1 = -1e30f;
    #pragma unroll
    for (int t = 0; t < 14; t++) {
        m0 = fmaxf(m0, fmaxf(acc[t][0], acc[t][1]));
        m1 = fmaxf(m1, fmaxf(acc[t][2], acc[t][3]));
    }
    m0 = fmaxf(m0, __shfl_xor_sync(0xffffffffu, m0, 1));
    m0 = fmaxf(m0, __shfl_xor_sync(0xffffffffu, m0, 2));
    m1 = fmaxf(m1, __shfl_xor_sync(0xffffffffu, m1, 1));
    m1 = fmaxf(m1, __shfl_xor_sync(0xffffffffu, m1, 2));
    if ((lane & 3) == 0) {
        redM[wn * 64 + row0]     = m0;
        redM[wn * 64 + row0 + 8] = m1;
    }
    __syncthreads();
    const float M0 = fmaxf(redM[row0],     redM[64 + row0]);
    const float M1 = fmaxf(redM[row0 + 8], redM[64 + row0 + 8]);

    float s0 = 0.f, s1 = 0.f;
    #pragma unroll
    for (int t = 0; t < 14; t++) {
        acc[t][0] = expf(acc[t][0] - M0);
        acc[t][1] = expf(acc[t][1] - M0);
        acc[t][2] = expf(acc[t][2] - M1);
        acc[t][3] = expf(acc[t][3] - M1);
        s0 += acc[t][0] + acc[t][1];
        s1 += acc[t][2] + acc[t][3];
    }
    s0 += __shfl_xor_sync(0xffffffffu, s0, 1);
    s0 += __shfl_xor_sync(0xffffffffu, s0, 2);
    s1 += __shfl_xor_sync(0xffffffffu, s1, 1);
    s1 += __shfl_xor_sync(0xffffffffu, s1, 2);
    if ((lane & 3) == 0) {
        redS[wn * 64 + row0]     = s0;
        redS[wn * 64 + row0 + 8] = s1;
    }
    __syncthreads();
    const float inv0 = 1.f / (redS[row0]     + redS[64 + row0]);
    const float inv1 = 1.f / (redS[row0 + 8] + redS[64 + row0 + 8]);

    // write fp16 attn weights (cols 0..223; invalid -> 0)
    #pragma unroll
    for (int t = 0; t < 14; t++) {
        int gc = wn * 112 + t * 8 + (lane & 3) * 2;
        *reinterpret_cast<uint32_t*>(&Ah[row0 * AT_ASTR + gc]) =
            pack_h2(acc[t][0] * inv0, acc[t][1] * inv0);
        *reinterpret_cast<uint32_t*>(&Ah[(row0 + 8) * AT_ASTR + gc]) =
            pack_h2(acc[t][2] * inv1, acc[t][3] * inv1);
    }
    __syncthreads();   // attn written; reuse Kh for V

    // ---- load V natural [kv][d] ----
    #pragma unroll
    for (int l = 0; l < 14; l++) {
        int idx = tid + l * 256;
        int r   = idx >> 4;
        int c4  = (idx & 15) << 2;
        uint2 v = make_uint2(0u, 0u);
        if (r < NTOK)
            v = *reinterpret_cast<const uint2*>(&Vb[(size_t)r * QS + c4]);
        *reinterpret_cast<uint32_t*>(&Kh[r * AT_KSTR + c4])     = v.x;
        *reinterpret_cast<uint32_t*>(&Kh[r * AT_KSTR + c4 + 2]) = v.y;
    }
    __syncthreads();

    // ---- phase 3: out = attn @ V (B-frags via ldmatrix.trans) ----
    float oac[4][4];
    #pragma unroll
    for (int t = 0; t < 4; t++)
        #pragma unroll
        for (int j = 0; j < 4; j++) oac[t][j] = 0.f;

    #pragma unroll
    for (int ks = 0; ks < 14; ks++) {
        const uint32_t kcb = (ks * 16 + ((lane >> 4) << 3)) * 2;
        uint32_t af[4];
        ldm_x4(af, uA + (uint32_t)(wm * 16 + (lane & 15)) * (AT_ASTR * 2) + kcb);
        #pragma unroll
        for (int g = 0; g < 2; g++) {
            uint32_t tb[4];
            uint32_t vaddr = uK
                + (uint32_t)(ks * 16 + (lane & 15)) * (AT_KSTR * 2)
                + (uint32_t)(wn * 32 + g * 16 + ((lane >> 4) << 3)) * 2;
            ldm_x4_trans(tb, vaddr);
            uint32_t b0[2] = {tb[0], tb[1]};
            uint32_t b1[2] = {tb[2], tb[3]};
            mma_f16(oac[g * 2 + 0], af, b0);
            mma_f16(oac[g * 2 + 1], af, b1);
        }
    }

    // ---- epilogue ----
    #pragma unroll
    for (int t = 0; t < 4; t++) {
        int gd = wn * 32 + t * 8 + (lane & 3) * 2;
        #pragma unroll
        for (int h = 0; h < 2; h++) {
            int qr = q0 + wm * 16 + (lane >> 2) + h * 8;
            if (qr >= NTOK) continue;
            size_t o = ((size_t)b * NTOK + qr) * EMB + hh * HD + gd;
            *reinterpret_cast<uint32_t*>(&th[o]) =
                pack_h2(oac[t][h * 2 + 0], oac[t][h * 2 + 1]);
        }
    }
}

// ------ fused split-K reduce (np partials) + bias + residual + LN + fp16 ----
__global__ __launch_bounds__(256)
void add_ln(const float* __restrict__ parts, int np, size_t pstride,
            const float* __restrict__ abias,
            const float* __restrict__ b,
            const float* __restrict__ g, const float* __restrict__ be,
            float* __restrict__ out, __half* __restrict__ oh)
{
    const int r   = blockIdx.x;
    const int tid = threadIdx.x;
    float v[3];
    float s = 0.f, q = 0.f;
    #pragma unroll
    for (int t = 0; t < 3; t++) {
        int c = tid + t * 256;
        size_t idx = (size_t)r * EMB + c;
        float acc = abias[c] + b[idx];
        for (int p = 0; p < np; p++)
            acc += parts[p * pstride + idx];
        v[t] = acc;
        s += v[t];
        q += v[t] * v[t];
    }
    #pragma unroll
    for (int o = 16; o; o >>= 1) {
        s += __shfl_xor_sync(0xffffffffu, s, o);
        q += __shfl_xor_sync(0xffffffffu, q, o);
    }
    __shared__ float red[2][8];
    int w = tid >> 5, lane = tid & 31;
    if (lane == 0) { red[0][w] = s; red[1][w] = q; }
    __syncthreads();
    s = 0.f; q = 0.f;
    #pragma unroll
    for (int i = 0; i < 8; i++) { s += red[0][i]; q += red[1][i]; }
    float mean = s * (1.f / EMB);
    float var  = q * (1.f / EMB) - mean * mean;
    float rstd = rsqrtf(var + EPS);
    #pragma unroll
    for (int t = 0; t < 3; t++) {
        int c = tid + t * 256;
        float o = (v[t] - mean) * rstd * g[c] + be[c];
        size_t idx = (size_t)r * EMB + c;
        out[idx] = o;
        oh[idx]  = __float2half_rn(o);
    }
}

__global__ __launch_bounds__(256)
void cls_ln(const float* __restrict__ h, const float* __restrict__ g,
            const float* __restrict__ be, float* __restrict__ out)
{
    const int b   = blockIdx.x;
    const int tid = threadIdx.x;
    const float* row = h + (size_t)b * NTOK * EMB;
    float v[3];
    float s = 0.f, q = 0.f;
    #pragma unroll
    for (int t = 0; t < 3; t++) {
        int c = tid + t * 256;
        v[t] = row[c];
        s += v[t];
        q += v[t] * v[t];
    }
    #pragma unroll
    for (int o = 16; o; o >>= 1) {
        s += __shfl_xor_sync(0xffffffffu, s, o);
        q += __shfl_xor_sync(0xffffffffu, q, o);
    }
    __shared__ float red[2][8];
    int w = tid >> 5, lane = tid & 31;
    if (lane == 0) { red[0][w] = s; red[1][w] = q; }
    __syncthreads();
    s = 0.f; q = 0.f;
    #pragma unroll
    for (int i = 0; i < 8; i++) { s += red[0][i]; q += red[1][i]; }
    float mean = s * (1.f / EMB);
    float var  = q * (1.f / EMB) - mean * mean;
    float rstd = rsqrtf(var + EPS);
    #pragma unroll
    for (int t = 0; t < 3; t++) {
        int c = tid + t * 256;
        out[(size_t)b * EMB + c] = (v[t] - mean) * rstd * g[c] + be[c];
    }
}

// ---------------- classifier head -------------------------------------------
__global__ __launch_bounds__(256)
void head_gemm(const float* __restrict__ cls, const float* __restrict__ W,
               const float* __restrict__ bias, float* __restrict__ out)
{
    int idx = blockIdx.x * blockDim.x + threadIdx.x;
    if (idx >= BATCH * NCLS) return;
    int b = idx / NCLS;
    int n = idx % NCLS;
    float s = bias[n];
    const float* c = cls + (size_t)b * EMB;
    for (int k = 0; k < EMB; k++)
        s = fmaf(c[k], W[(size_t)k * NCLS + n], s);
    out[idx] = s;
}

// ---------------- driver -----------------------------------------------------
extern "C" void kernel_launch(void* const* d_in, const int* in_sizes, int n_in,
                              void* d_out, int out_size)
{
    const float* x        = (const float*)d_in[0];
    const float* conv_w   = (const float*)d_in[1];
    const float* conv_b   = (const float*)d_in[2];
    const float* cls_tok  = (const float*)d_in[3];
    const float* pos_emb  = (const float*)d_in[4];
    const float* Wq       = (const float*)d_in[5];
    const float* Wk       = (const float*)d_in[6];
    const float* Wv       = (const float*)d_in[7];
    const float* Wo       = (const float*)d_in[8];
    const float* bo       = (const float*)d_in[9];
    const float* ln1_g    = (const float*)d_in[10];
    const float* ln1_b    = (const float*)d_in[11];
    const float* W1       = (const float*)d_in[12];
    const float* b1       = (const float*)d_in[13];
    const float* W2       = (const float*)d_in[14];
    const float* b2       = (const float*)d_in[15];
    const float* ln2_g    = (const float*)d_in[16];
    const float* ln2_b    = (const float*)d_in[17];
    const float* head_g   = (const float*)d_in[18];
    const float* head_b   = (const float*)d_in[19];
    const float* head_W   = (const float*)d_in[20];
    const float* head_bias= (const float*)d_in[21];
    float* out = (float*)d_out;

    float *ph, *px, *pt, *pcls;
    __half *pqkv, *phh, *pxh, *pth, *pfh, *pimh, *pw, *pcw;
    cudaGetSymbolAddress((void**)&ph,   g_h);
    cudaGetSymbolAddress((void**)&px,   g_x);
    cudaGetSymbolAddress((void**)&pt,   g_t);
    cudaGetSymbolAddress((void**)&pcls, g_cls);
    cudaGetSymbolAddress((void**)&pqkv, g_qkv);
    cudaGetSymbolAddress((void**)&phh,  g_hh);
    cudaGetSymbolAddress((void**)&pxh,  g_xh);
    cudaGetSymbolAddress((void**)&pth,  g_th);
    cudaGetSymbolAddress((void**)&pfh,  g_fh);
    cudaGetSymbolAddress((void**)&pimh, g_imh);
    cudaGetSymbolAddress((void**)&pw,   g_w);
    cudaGetSymbolAddress((void**)&pcw,  g_cw);
    const size_t PSTR = (size_t)ROWS * EMB;

    cudaFuncSetAttribute(gemm_hmma, cudaFuncAttributeMaxDynamicSharedMemorySize,
                         GEMM_SMEM);
    cudaFuncSetAttribute(attn_tc, cudaFuncAttributeMaxDynamicSharedMemorySize,
                         ATT_SMEM);

    // ---- weight prep: batched transpose to [N,K] fp16 ----
    {
        dim3 blk(32, 8);
        dim3 gEE(EMB/32, EMB/32, DEPTH);
        transpose_half_batch<<<gEE, blk>>>(Wq, pw + OFF_Q, EMB, EMB,
                                           (size_t)EMB*EMB, LSTRIDE);
        transpose_half_batch<<<gEE, blk>>>(Wk, pw + OFF_K, EMB, EMB,
                                           (size_t)EMB*EMB, LSTRIDE);
        transpose_half_batch<<<gEE, blk>>>(Wv, pw + OFF_V, EMB, EMB,
                                           (size_t)EMB*EMB, LSTRIDE);
        transpose_half_batch<<<gEE, blk>>>(Wo, pw + OFF_O, EMB, EMB,
                                           (size_t)EMB*EMB, LSTRIDE);
        dim3 g1(FF/32, EMB/32, DEPTH);
        transpose_half_batch<<<g1, blk>>>(W1, pw + OFF_W1, EMB, FF,
                                          (size_t)EMB*FF, LSTRIDE);
        dim3 g2(EMB/32, FF/32, DEPTH);
        transpose_half_batch<<<g2, blk>>>(W2, pw + OFF_W2, FF, EMB,
                                          (size_t)FF*EMB, LSTRIDE);
        tohalf_only<<<(EMB*EMB + 255)/256, 256>>>(conv_w, pcw, EMB*EMB);
    }

    // ---- patch embedding ----
    im2col_kernel<<<(PROWS*EMB + 255)/256, 256>>>(x, pimh);
    gemm_hmma<<<dim3(EMB/BN, PROWS/BM, 1), 256, GEMM_SMEM>>>(
        pimh, pcw, conv_b, pt, nullptr, PROWS, EMB, EMB, EMB, 0);
    embed_kernel<<<(ROWS*EMB + 255)/256, 256>>>(pt, cls_tok, pos_emb, ph, phh);

    const int mtiles = (ROWS + BM - 1) / BM;     // 50
    const dim3 gQKV(QS/BN, mtiles, 1);           // 18 x 50
    const dim3 gEs(EMB/BN, mtiles, NSPLIT);      // 6 x 50 x 4 (split-K4)
    const dim3 gF1(FF/BN,  mtiles, 1);           // 24 x 50
    const dim3 gAT(4, BATCH*NHEAD);

    for (int l = 0; l < DEPTH; l++) {
        size_t base = (size_t)l * LSTRIDE;
        const __half* qkvw = pw + base + OFF_Q;   // [2304, 768]
        const __half* ow   = pw + base + OFF_O;
        const __half* w1w  = pw + base + OFF_W1;
        const __half* w2w  = pw + base + OFF_W2;
        const float* bol= bo + (size_t)l*EMB;
        const float* g1 = ln1_g + (size_t)l*EMB;
        const float* be1= ln1_b + (size_t)l*EMB;
        const float* bb1= b1 + (size_t)l*FF;
        const float* bb2= b2 + (size_t)l*EMB;
        const float* g2 = ln2_g + (size_t)l*EMB;
        const float* be2= ln2_b + (size_t)l*EMB;

        // QKV emits fp16 directly
        gemm_hmma<<<gQKV, 256, GEMM_SMEM>>>(phh, qkvw, nullptr,
                                            nullptr, pqkv, ROWS, QS, EMB, EMB, 0);

        attn_tc<<<gAT, 256, ATT_SMEM>>>(pqkv, pth);

        // O-proj split-K4: partials in pt[0..3]; bias folded into add_ln
        gemm_hmma<<<gEs, 256, GEMM_SMEM>>>(pth, ow, nullptr,
                                           pt, nullptr, ROWS, EMB,
                                           EMB / NSPLIT, EMB, 0);
        add_ln<<<ROWS, 256>>>(pt, NSPLIT, PSTR, bol, ph, g1, be1, px, pxh);

        gemm_hmma<<<gF1, 256, GEMM_SMEM>>>(pxh, w1w, bb1,
                                           nullptr, pfh, ROWS, FF, EMB, EMB, 1);
        // FF2 split-K4
        gemm_hmma<<<gEs, 256, GEMM_SMEM>>>(pfh, w2w, nullptr,
                                           pt, nullptr, ROWS, EMB,
                                           FF / NSPLIT, FF, 0);
        add_ln<<<ROWS, 256>>>(pt, NSPLIT, PSTR, bb2, px, g2, be2, ph, phh);
    }

    cls_ln<<<BATCH, 256>>>(ph, head_g, head_b, pcls);
    head_gemm<<<(BATCH*NCLS + 255)/256, 256>>>(pcls, head_W, head_bias, out);
}

// round 15
// speedup vs baseline: 1.0871x; 1.0871x over previous
#include <cuda_runtime.h>
#include <cuda_fp16.h>
#include <cstdint>
#include <cstddef>

// ---------------- Problem constants ----------------
#define IMG   224
#define PATCH 16
#define EMB   768
#define DEPTH 12
#define NHEAD 12
#define HD    64
#define FF    3072
#define NCLS  1000
#define BATCH 32
#define NP    196
#define NTOK  197
#define ROWS  (BATCH * NTOK) // 6304
#define PROWS (BATCH * NP)   // 6272
#define EPS   1e-5f
#define QS    2304           // fused qkv row stride
#define NSPLIT 2             // split-K factor for O-proj / FF2

// weight layout (per layer, element offsets). Q,K,V contiguous -> fused QKV.
#define OFF_Q   0
#define OFF_K   589824
#define OFF_V   1179648
#define OFF_O   1769472
#define OFF_W1  2359296
#define OFF_W2  4718592
#define LSTRIDE 7077888
#define WTOTAL  (LSTRIDE * DEPTH)

// ---------------- Scratch ----------------
__device__ float g_h  [ROWS * EMB];             // trunk fp32
__device__ float g_x  [ROWS * EMB];             // post-LN1 fp32
__device__ float g_t  [NSPLIT * ROWS * EMB];    // split-K partial buffers
__device__ float g_cls[BATCH * EMB];
__device__ __half g_qkv[ROWS * QS];             // fused qkv fp16
__device__ __half g_hh [ROWS * EMB];
__device__ __half g_xh [ROWS * EMB];
__device__ __half g_th [ROWS * EMB];
__device__ __half g_fh [ROWS * FF];
__device__ __half g_imh[PROWS * EMB];
__device__ __half g_w  [WTOTAL];                // weights fp16, [N,K]
__device__ __half g_cw [EMB * EMB];

// ---------------- helpers ----------------
__device__ __forceinline__ uint32_t smem_u32(const void* p) {
    uint32_t a;
    asm("{ .reg .u64 t; cvta.to.shared.u64 t, %1; cvt.u32.u64 %0, t; }"
        : "=r"(a) : "l"(p));
    return a;
}
__device__ __forceinline__ void ldm_x4(uint32_t (&r)[4], uint32_t addr) {
    asm volatile("ldmatrix.sync.aligned.m8n8.x4.shared.b16 {%0,%1,%2,%3}, [%4];"
                 : "=r"(r[0]), "=r"(r[1]), "=r"(r[2]), "=r"(r[3]) : "r"(addr));
}
__device__ __forceinline__ void ldm_x4_trans(uint32_t (&r)[4], uint32_t addr) {
    asm volatile("ldmatrix.sync.aligned.m8n8.x4.trans.shared.b16 {%0,%1,%2,%3}, [%4];"
                 : "=r"(r[0]), "=r"(r[1]), "=r"(r[2]), "=r"(r[3]) : "r"(addr));
}
__device__ __forceinline__ void mma_f16(float (&d)[4], const uint32_t (&a)[4],
                                        const uint32_t (&b)[2]) {
    asm volatile("mma.sync.aligned.m16n8k16.row.col.f32.f16.f16.f32 "
                 "{%0,%1,%2,%3}, {%4,%5,%6,%7}, {%8,%9}, {%0,%1,%2,%3};"
                 : "+f"(d[0]), "+f"(d[1]), "+f"(d[2]), "+f"(d[3])
                 : "r"(a[0]), "r"(a[1]), "r"(a[2]), "r"(a[3]),
                   "r"(b[0]), "r"(b[1]));
}
__device__ __forceinline__ uint32_t pack_h2(float x, float y) {
    __half2 h = __floats2half2_rn(x, y);
    return *reinterpret_cast<uint32_t*>(&h);
}

// ---------------- weight prep: transpose [K,N] -> [N,K], fp16 ---------------
__global__ void transpose_half_batch(const float* __restrict__ W,
                                     __half* __restrict__ out,
                                     int K, int N,
                                     size_t w_lstride, size_t o_lstride)
{
    __shared__ float t[32][33];
    const int layer = blockIdx.z;
    W   += (size_t)layer * w_lstride;
    out += (size_t)layer * o_lstride;
    int nb = blockIdx.x * 32, kb = blockIdx.y * 32;
    int tx = threadIdx.x, ty = threadIdx.y;
    #pragma unroll
    for (int j = ty; j < 32; j += 8)
        t[j][tx] = W[(size_t)(kb + j) * N + nb + tx];
    __syncthreads();
    #pragma unroll
    for (int j = ty; j < 32; j += 8)
        out[(size_t)(nb + j) * K + kb + tx] = __float2half_rn(t[tx][j]);
}

__global__ void tohalf_only(const float* __restrict__ W,
                            __half* __restrict__ out, int n)
{
    int i = blockIdx.x * blockDim.x + threadIdx.x;
    if (i < n) out[i] = __float2half_rn(W[i]);
}

// ---------------- pipelined HMMA GEMM (single-pass fp16, fp32 accum) --------
#define BM 128
#define BN 128
#define BK 64
#define ROWB 144                    // 64*2 + 16 pad bytes per smem row
#define ARR_B (128 * ROWB)          // 18432
#define STAGE_B (2 * ARR_B)         // 36864
#define GEMM_SMEM (3 * STAGE_B)     // 110592 (3-stage)

__global__ __launch_bounds__(256, 2)
void gemm_hmma(const __half* __restrict__ A,
               const __half* __restrict__ B,
               const float* __restrict__ bias,
               float* __restrict__ Cf,
               __half* __restrict__ Ch,
               int M, int N, int Kspan, int ldK, int do_relu)
{
    extern __shared__ __align__(16) unsigned char dsm[];
    const uint32_t smb = smem_u32(dsm);
    const int tid  = threadIdx.x;
    const int lane = tid & 31;
    const int wid  = tid >> 5;
    const int wm   = wid & 1;
    const int wn   = wid >> 1;
    const int row0 = blockIdx.y * BM;
    const int col0 = blockIdx.x * BN;
    const int kz   = blockIdx.z;

    const __half* Ab = A + (size_t)kz * Kspan;
    const __half* Bb = B + (size_t)kz * Kspan;
    if (Cf) Cf += (size_t)kz * M * N;

    float acc[4][4][4] = {};

    auto load_stage = [&](int s, int kt) {
        #pragma unroll
        for (int l = 0; l < 8; l++) {
            int idx = tid + l * 256;
            int arr = idx >> 10;
            int w   = idx & 1023;
            int r   = w >> 3;
            int q   = w & 7;
            int row = (arr ? col0 : row0) + r;
            const __half* src = (arr ? Bb : Ab) + (size_t)row * ldK + kt + q * 8;
            int bytes = (!arr && row >= M) ? 0 : 16;
            uint32_t dst = smb + (uint32_t)s * STAGE_B + (uint32_t)arr * ARR_B
                         + (uint32_t)r * ROWB + (uint32_t)q * 16u;
            asm volatile("cp.async.cg.shared.global [%0], [%1], 16, %2;"
                         :: "r"(dst), "l"(src), "r"(bytes) : "memory");
        }
        asm volatile("cp.async.commit_group;" ::: "memory");
    };

    auto compute_stage = [&](int s) {
        const uint32_t uA = smb + (uint32_t)s * STAGE_B;
        const uint32_t uB = uA + ARR_B;
        #pragma unroll
        for (int kk = 0; kk < 4; kk++) {
            const uint32_t kcb = (kk * 16 + ((lane >> 4) << 3)) * 2;
            uint32_t af[4][4];
            uint32_t bf[4][2];
            #pragma unroll
            for (int mi = 0; mi < 4; mi++) {
                uint32_t off = (uint32_t)(wm * 64 + mi * 16 + (lane & 15)) * ROWB + kcb;
                ldm_x4(af[mi], uA + off);
            }
            #pragma unroll
            for (int g = 0; g < 2; g++) {
                uint32_t off = (uint32_t)(wn * 32 + g * 16 + (lane & 15)) * ROWB + kcb;
                uint32_t tb[4];
                ldm_x4(tb, uB + off);
                bf[g*2+0][0] = tb[0]; bf[g*2+0][1] = tb[2];
                bf[g*2+1][0] = tb[1]; bf[g*2+1][1] = tb[3];
            }
            #pragma unroll
            for (int mi = 0; mi < 4; mi++)
                #pragma unroll
                for (int n = 0; n < 4; n++)
                    mma_f16(acc[mi][n], af[mi], bf[n]);
        }
    };

    const int nk = Kspan / BK;          // >= 6 for all launched shapes
    load_stage(0, 0);
    load_stage(1, BK);
    for (int i = 0; i < nk; i++) {
        if (i == nk - 1)
            asm volatile("cp.async.wait_group 0;" ::: "memory");
        else
            asm volatile("cp.async.wait_group 1;" ::: "memory");
        __syncthreads();    // group i visible; all threads done computing stage (i-1)
        if (i + 2 < nk)
            load_stage((i + 2) % 3, (i + 2) * BK);
        compute_stage(i % 3);
    }

    // ---- epilogue ----
    const bool hb = (bias != nullptr);
    #pragma unroll
    for (int mi = 0; mi < 4; mi++) {
        #pragma unroll
        for (int n = 0; n < 4; n++) {
            int gc = col0 + wn * 32 + n * 8 + (lane & 3) * 2;
            float bx = 0.f, by = 0.f;
            if (hb) { bx = bias[gc]; by = bias[gc + 1]; }
            #pragma unroll
            for (int h = 0; h < 2; h++) {
                int gr = row0 + wm * 64 + mi * 16 + (lane >> 2) + h * 8;
                if (gr >= M) continue;
                float ox = acc[mi][n][h * 2 + 0] + bx;
                float oy = acc[mi][n][h * 2 + 1] + by;
                if (do_relu) { ox = fmaxf(ox, 0.f); oy = fmaxf(oy, 0.f); }
                size_t o = (size_t)gr * N + gc;
                if (Cf)
                    *reinterpret_cast<float2*>(&Cf[o]) = make_float2(ox, oy);
                if (Ch)
                    *reinterpret_cast<uint32_t*>(&Ch[o]) = pack_h2(ox, oy);
            }
        }
    }
}

// ---------------- im2col (emits fp16) ---------------------------------------
__global__ void im2col_kernel(const float* __restrict__ x,
                              __half* __restrict__ ho)
{
    int idx = blockIdx.x * blockDim.x + threadIdx.x;
    if (idx >= PROWS * EMB) return;
    int row = idx / EMB;
    int k   = idx % EMB;
    int b   = row / NP;
    int p   = row % NP;
    int py  = p / 14, px = p % 14;
    int c   = k / 256;
    int r2  = k % 256;
    int ph  = r2 / PATCH, pw = r2 % PATCH;
    float v = x[(((size_t)b * 3 + c) * IMG + (py * PATCH + ph)) * IMG
                + (px * PATCH + pw)];
    ho[idx] = __float2half_rn(v);
}

__global__ void embed_kernel(const float* __restrict__ patch,
                             const float* __restrict__ cls_tok,
                             const float* __restrict__ pos,
                             float* __restrict__ h,
                             __half* __restrict__ hh)
{
    int idx = blockIdx.x * blockDim.x + threadIdx.x;
    if (idx >= ROWS * EMB) return;
    int row = idx / EMB;
    int e   = idx % EMB;
    int b   = row / NTOK;
    int n   = row % NTOK;
    float base = (n == 0) ? cls_tok[e]
                          : patch[((size_t)b * NP + (n - 1)) * EMB + e];
    float v = base + pos[n * EMB + e];
    h[idx]  = v;
    hh[idx] = __float2half_rn(v);
}

// ---------------- tensor-core fused attention --------------------------------
#define AT_QSTR 72
#define AT_KSTR 72
#define AT_ASTR 232
#define AT_Q_OFF   0
#define AT_KV_OFF  9216          // 64*72*2
#define AT_A_OFF   41472         // 9216 + 224*72*2
#define AT_RED_OFF 71168         // 41472 + 64*232*2
#define ATT_SMEM   72192         // + 256*4

__global__ __launch_bounds__(256, 2)
void attn_tc(const __half* __restrict__ qkv, __half* __restrict__ th)
{
    extern __shared__ __align__(16) char smc[];
    __half* Qh = reinterpret_cast<__half*>(smc + AT_Q_OFF);
    __half* Kh = reinterpret_cast<__half*>(smc + AT_KV_OFF);   // K, then V
    __half* Ah = reinterpret_cast<__half*>(smc + AT_A_OFF);
    float* redM = reinterpret_cast<float*>(smc + AT_RED_OFF);  // [2][64]
    float* redS = redM + 128;                                  // [2][64]

    const int bh = blockIdx.y;
    const int b  = bh / NHEAD;
    const int hh = bh % NHEAD;
    const int q0 = blockIdx.x * 64;
    const float scale = 0.036084391824f;   // 1/sqrt(768)

    const int tid  = threadIdx.x;
    const int lane = tid & 31;
    const int wid  = tid >> 5;
    const int wm   = wid & 3;
    const int wn   = wid >> 2;

    const __half* Qb = qkv + (size_t)b * NTOK * QS + hh * HD;
    const __half* Kb = Qb + 768;
    const __half* Vb = Qb + 1536;

    const uint32_t uQ = smem_u32(Qh);
    const uint32_t uK = smem_u32(Kh);
    const uint32_t uA = smem_u32(Ah);

    // ---- load Q (64 x 64) ----
    #pragma unroll
    for (int l = 0; l < 4; l++) {
        int idx = tid + l * 256;
        int r   = idx >> 4;
        int c4  = (idx & 15) << 2;
        uint2 v = make_uint2(0u, 0u);
        if (q0 + r < NTOK)
            v = *reinterpret_cast<const uint2*>(&Qb[(size_t)(q0 + r) * QS + c4]);
        *reinterpret_cast<uint32_t*>(&Qh[r * AT_QSTR + c4])     = v.x;
        *reinterpret_cast<uint32_t*>(&Qh[r * AT_QSTR + c4 + 2]) = v.y;
    }
    // ---- load K (224 x 64, zero-padded past NTOK) ----
    #pragma unroll
    for (int l = 0; l < 14; l++) {
        int idx = tid + l * 256;
        int r   = idx >> 4;
        int c4  = (idx & 15) << 2;
        uint2 v = make_uint2(0u, 0u);
        if (r < NTOK)
            v = *reinterpret_cast<const uint2*>(&Kb[(size_t)r * QS + c4]);
        *reinterpret_cast<uint32_t*>(&Kh[r * AT_KSTR + c4])     = v.x;
        *reinterpret_cast<uint32_t*>(&Kh[r * AT_KSTR + c4 + 2]) = v.y;
    }
    __syncthreads();

    // ---- phase 1: scores via mma ----
    float acc[14][4];
    #pragma unroll
    for (int t = 0; t < 14; t++)
        #pragma unroll
        for (int j = 0; j < 4; j++) acc[t][j] = 0.f;

    #pragma unroll
    for (int ks = 0; ks < 4; ks++) {
        const uint32_t kcb = (ks * 16 + ((lane >> 4) << 3)) * 2;
        uint32_t af[4];
        ldm_x4(af, uQ + (uint32_t)(wm * 16 + (lane & 15)) * (AT_QSTR * 2) + kcb);
        #pragma unroll
        for (int g = 0; g < 7; g++) {
            uint32_t tb[4];
            ldm_x4(tb, uK + (uint32_t)(wn * 112 + g * 16 + (lane & 15)) * (AT_KSTR * 2) + kcb);
            uint32_t b0[2] = {tb[0], tb[2]};
            uint32_t b1[2] = {tb[1], tb[3]};
            mma_f16(acc[g * 2 + 0], af, b0);
            mma_f16(acc[g * 2 + 1], af, b1);
        }
    }

    // ---- register softmax ----
    const int row0 = wm * 16 + (lane >> 2);
    const int cb   = wn * 112 + (lane & 3) * 2;
    #pragma unroll
    for (int t = 0; t < 14; t++) {
        #pragma unroll
        for (int j = 0; j < 4; j++) {
            int gc = cb + t * 8 + (j & 1);
            float v = acc[t][j] * scale;
            acc[t][j] = (gc < NTOK) ? v : -1e30f;
        }
    }
    float m0 = -1e30f, m1 = -1e30f;
    #pragma unroll
    for (int t = 0; t < 14; t++) {
        m0 = fmaxf(m0, fmaxf(acc[t][0], acc[t][1]));
        m1 = fmaxf(m1, fmaxf(acc[t][2], acc[t][3]));
    }
    m0 = fmaxf(m0, __shfl_xor_sync(0xffffffffu, m0, 1));
    m0 = fmaxf(m0, __shfl_xor_sync(0xffffffffu, m0, 2));
    m1 = fmaxf(m1, __shfl_xor_sync(0xffffffffu, m1, 1));
    m1 = fmaxf(m1, __shfl_xor_sync(0xffffffffu, m1, 2));
    if ((lane & 3) == 0) {
        redM[wn * 64 + row0]     = m0;
        redM[wn * 64 + row0 + 8] = m1;
    }
    __syncthreads();
    const float M0 = fmaxf(redM[row0],     redM[64 + row0]);
    const float M1 = fmaxf(redM[row0 + 8], redM[64 + row0 + 8]);

    float s0 = 0.f, s1 = 0.f;
    #pragma unroll
    for (int t = 0; t < 14; t++) {
        acc[t][0] = expf(acc[t][0] - M0);
        acc[t][1] = expf(acc[t][1] - M0);
        acc[t][2] = expf(acc[t][2] - M1);
        acc[t][3] = expf(acc[t][3] - M1);
        s0 += acc[t][0] + acc[t][1];
        s1 += acc[t][2] + acc[t][3];
    }
    s0 += __shfl_xor_sync(0xffffffffu, s0, 1);
    s0 += __shfl_xor_sync(0xffffffffu, s0, 2);
    s1 += __shfl_xor_sync(0xffffffffu, s1, 1);
    s1 += __shfl_xor_sync(0xffffffffu, s1, 2);
    if ((lane & 3) == 0) {
        redS[wn * 64 + row0]     = s0;
        redS[wn * 64 + row0 + 8] = s1;
    }
    __syncthreads();
    const float inv0 = 1.f / (redS[row0]     + redS[64 + row0]);
    const float inv1 = 1.f / (redS[row0 + 8] + redS[64 + row0 + 8]);

    // write fp16 attn weights (cols 0..223; invalid -> 0)
    #pragma unroll
    for (int t = 0; t < 14; t++) {
        int gc = wn * 112 + t * 8 + (lane & 3) * 2;
        *reinterpret_cast<uint32_t*>(&Ah[row0 * AT_ASTR + gc]) =
            pack_h2(acc[t][0] * inv0, acc[t][1] * inv0);
        *reinterpret_cast<uint32_t*>(&Ah[(row0 + 8) * AT_ASTR + gc]) =
            pack_h2(acc[t][2] * inv1, acc[t][3] * inv1);
    }
    __syncthreads();   // attn written; reuse Kh for V

    // ---- load V natural [kv][d] ----
    #pragma unroll
    for (int l = 0; l < 14; l++) {
        int idx = tid + l * 256;
        int r   = idx >> 4;
        int c4  = (idx & 15) << 2;
        uint2 v = make_uint2(0u, 0u);
        if (r < NTOK)
            v = *reinterpret_cast<const uint2*>(&Vb[(size_t)r * QS + c4]);
        *reinterpret_cast<uint32_t*>(&Kh[r * AT_KSTR + c4])     = v.x;
        *reinterpret_cast<uint32_t*>(&Kh[r * AT_KSTR + c4 + 2]) = v.y;
    }
    __syncthreads();

    // ---- phase 3: out = attn @ V (B-frags via ldmatrix.trans) ----
    float oac[4][4];
    #pragma unroll
    for (int t = 0; t < 4; t++)
        #pragma unroll
        for (int j = 0; j < 4; j++) oac[t][j] = 0.f;

    #pragma unroll
    for (int ks = 0; ks < 14; ks++) {
        const uint32_t kcb = (ks * 16 + ((lane >> 4) << 3)) * 2;
        uint32_t af[4];
        ldm_x4(af, uA + (uint32_t)(wm * 16 + (lane & 15)) * (AT_ASTR * 2) + kcb);
        #pragma unroll
        for (int g = 0; g < 2; g++) {
            uint32_t tb[4];
            uint32_t vaddr = uK
                + (uint32_t)(ks * 16 + (lane & 15)) * (AT_KSTR * 2)
                + (uint32_t)(wn * 32 + g * 16 + ((lane >> 4) << 3)) * 2;
            ldm_x4_trans(tb, vaddr);
            uint32_t b0[2] = {tb[0], tb[1]};
            uint32_t b1[2] = {tb[2], tb[3]};
            mma_f16(oac[g * 2 + 0], af, b0);
            mma_f16(oac[g * 2 + 1], af, b1);
        }
    }

    // ---- epilogue ----
    #pragma unroll
    for (int t = 0; t < 4; t++) {
        int gd = wn * 32 + t * 8 + (lane & 3) * 2;
        #pragma unroll
        for (int h = 0; h < 2; h++) {
            int qr = q0 + wm * 16 + (lane >> 2) + h * 8;
            if (qr >= NTOK) continue;
            size_t o = ((size_t)b * NTOK + qr) * EMB + hh * HD + gd;
            *reinterpret_cast<uint32_t*>(&th[o]) =
                pack_h2(oac[t][h * 2 + 0], oac[t][h * 2 + 1]);
        }
    }
}

// ------ fused split-K2 reduce + bias + residual + LN + fp16 (float4 wide) ---
__global__ __launch_bounds__(192)
void add_ln(const float* __restrict__ p0, const float* __restrict__ p1,
            const float* __restrict__ abias,
            const float* __restrict__ b,
            const float* __restrict__ g, const float* __restrict__ be,
            float* __restrict__ out, __half* __restrict__ oh)
{
    const int r   = blockIdx.x;
    const int tid = threadIdx.x;     // 192 threads, 4 floats each
    const int c   = tid * 4;
    const size_t idx = (size_t)r * EMB + c;

    float4 v  = *reinterpret_cast<const float4*>(&p0[idx]);
    float4 v1 = *reinterpret_cast<const float4*>(&p1[idx]);
    float4 bb = *reinterpret_cast<const float4*>(&b[idx]);
    float4 ab = *reinterpret_cast<const float4*>(&abias[c]);
    v.x += v1.x + bb.x + ab.x;
    v.y += v1.y + bb.y + ab.y;
    v.z += v1.z + bb.z + ab.z;
    v.w += v1.w + bb.w + ab.w;

    float s = v.x + v.y + v.z + v.w;
    float q = v.x * v.x + v.y * v.y + v.z * v.z + v.w * v.w;
    #pragma unroll
    for (int o = 16; o; o >>= 1) {
        s += __shfl_xor_sync(0xffffffffu, s, o);
        q += __shfl_xor_sync(0xffffffffu, q, o);
    }
    __shared__ float red[2][6];
    int w = tid >> 5, lane = tid & 31;
    if (lane == 0) { red[0][w] = s; red[1][w] = q; }
    __syncthreads();
    s = 0.f; q = 0.f;
    #pragma unroll
    for (int i = 0; i < 6; i++) { s += red[0][i]; q += red[1][i]; }
    const float mean = s * (1.f / EMB);
    const float var  = q * (1.f / EMB) - mean * mean;
    const float rstd = rsqrtf(var + EPS);

    float4 gg = *reinterpret_cast<const float4*>(&g[c]);
    float4 ee = *reinterpret_cast<const float4*>(&be[c]);
    float4 o;
    o.x = (v.x - mean) * rstd * gg.x + ee.x;
    o.y = (v.y - mean) * rstd * gg.y + ee.y;
    o.z = (v.z - mean) * rstd * gg.z + ee.z;
    o.w = (v.w - mean) * rstd * gg.w + ee.w;
    *reinterpret_cast<float4*>(&out[idx]) = o;
    uint2 hp;
    hp.x = pack_h2(o.x, o.y);
    hp.y = pack_h2(o.z, o.w);
    *reinterpret_cast<uint2*>(&oh[idx]) = hp;
}

__global__ __launch_bounds__(256)
void cls_ln(const float* __restrict__ h, const float* __restrict__ g,
            const float* __restrict__ be, float* __restrict__ out)
{
    const int b   = blockIdx.x;
    const int tid = threadIdx.x;
    const float* row = h + (size_t)b * NTOK * EMB;
    float v[3];
    float s = 0.f, q = 0.f;
    #pragma unroll
    for (int t = 0; t < 3; t++) {
        int c = tid + t * 256;
        v[t] = row[c];
        s += v[t];
        q += v[t] * v[t];
    }
    #pragma unroll
    for (int o = 16; o; o >>= 1) {
        s += __shfl_xor_sync(0xffffffffu, s, o);
        q += __shfl_xor_sync(0xffffffffu, q, o);
    }
    __shared__ float red[2][8];
    int w = tid >> 5, lane = tid & 31;
    if (lane == 0) { red[0][w] = s; red[1][w] = q; }
    __syncthreads();
    s = 0.f; q = 0.f;
    #pragma unroll
    for (int i = 0; i < 8; i++) { s += red[0][i]; q += red[1][i]; }
    float mean = s * (1.f / EMB);
    float var  = q * (1.f / EMB) - mean * mean;
    float rstd = rsqrtf(var + EPS);
    #pragma unroll
    for (int t = 0; t < 3; t++) {
        int c = tid + t * 256;
        out[(size_t)b * EMB + c] = (v[t] - mean) * rstd * g[c] + be[c];
    }
}

// ---------------- classifier head -------------------------------------------
__global__ __launch_bounds__(256)
void head_gemm(const float* __restrict__ cls, const float* __restrict__ W,
               const float* __restrict__ bias, float* __restrict__ out)
{
    int idx = blockIdx.x * blockDim.x + threadIdx.x;
    if (idx >= BATCH * NCLS) return;
    int b = idx / NCLS;
    int n = idx % NCLS;
    float s = bias[n];
    const float* c = cls + (size_t)b * EMB;
    for (int k = 0; k < EMB; k++)
        s = fmaf(c[k], W[(size_t)k * NCLS + n], s);
    out[idx] = s;
}

// ---------------- driver -----------------------------------------------------
extern "C" void kernel_launch(void* const* d_in, const int* in_sizes, int n_in,
                              void* d_out, int out_size)
{
    const float* x        = (const float*)d_in[0];
    const float* conv_w   = (const float*)d_in[1];
    const float* conv_b   = (const float*)d_in[2];
    const float* cls_tok  = (const float*)d_in[3];
    const float* pos_emb  = (const float*)d_in[4];
    const float* Wq       = (const float*)d_in[5];
    const float* Wk       = (const float*)d_in[6];
    const float* Wv       = (const float*)d_in[7];
    const float* Wo       = (const float*)d_in[8];
    const float* bo       = (const float*)d_in[9];
    const float* ln1_g    = (const float*)d_in[10];
    const float* ln1_b    = (const float*)d_in[11];
    const float* W1       = (const float*)d_in[12];
    const float* b1       = (const float*)d_in[13];
    const float* W2       = (const float*)d_in[14];
    const float* b2       = (const float*)d_in[15];
    const float* ln2_g    = (const float*)d_in[16];
    const float* ln2_b    = (const float*)d_in[17];
    const float* head_g   = (const float*)d_in[18];
    const float* head_b   = (const float*)d_in[19];
    const float* head_W   = (const float*)d_in[20];
    const float* head_bias= (const float*)d_in[21];
    float* out = (float*)d_out;

    float *ph, *px, *pt, *pcls;
    __half *pqkv, *phh, *pxh, *pth, *pfh, *pimh, *pw, *pcw;
    cudaGetSymbolAddress((void**)&ph,   g_h);
    cudaGetSymbolAddress((void**)&px,   g_x);
    cudaGetSymbolAddress((void**)&pt,   g_t);
    cudaGetSymbolAddress((void**)&pcls, g_cls);
    cudaGetSymbolAddress((void**)&pqkv, g_qkv);
    cudaGetSymbolAddress((void**)&phh,  g_hh);
    cudaGetSymbolAddress((void**)&pxh,  g_xh);
    cudaGetSymbolAddress((void**)&pth,  g_th);
    cudaGetSymbolAddress((void**)&pfh,  g_fh);
    cudaGetSymbolAddress((void**)&pimh, g_imh);
    cudaGetSymbolAddress((void**)&pw,   g_w);
    cudaGetSymbolAddress((void**)&pcw,  g_cw);
    float* pt2 = pt + (size_t)ROWS * EMB;

    cudaFuncSetAttribute(gemm_hmma, cudaFuncAttributeMaxDynamicSharedMemorySize,
                         GEMM_SMEM);
    cudaFuncSetAttribute(attn_tc, cudaFuncAttributeMaxDynamicSharedMemorySize,
                         ATT_SMEM);

    // ---- weight prep: batched transpose to [N,K] fp16 ----
    {
        dim3 blk(32, 8);
        dim3 gEE(EMB/32, EMB/32, DEPTH);
        transpose_half_batch<<<gEE, blk>>>(Wq, pw + OFF_Q, EMB, EMB,
                                           (size_t)EMB*EMB, LSTRIDE);
        transpose_half_batch<<<gEE, blk>>>(Wk, pw + OFF_K, EMB, EMB,
                                           (size_t)EMB*EMB, LSTRIDE);
        transpose_half_batch<<<gEE, blk>>>(Wv, pw + OFF_V, EMB, EMB,
                                           (size_t)EMB*EMB, LSTRIDE);
        transpose_half_batch<<<gEE, blk>>>(Wo, pw + OFF_O, EMB, EMB,
                                           (size_t)EMB*EMB, LSTRIDE);
        dim3 g1(FF/32, EMB/32, DEPTH);
        transpose_half_batch<<<g1, blk>>>(W1, pw + OFF_W1, EMB, FF,
                                          (size_t)EMB*FF, LSTRIDE);
        dim3 g2(EMB/32, FF/32, DEPTH);
        transpose_half_batch<<<g2, blk>>>(W2, pw + OFF_W2, FF, EMB,
                                          (size_t)FF*EMB, LSTRIDE);
        tohalf_only<<<(EMB*EMB + 255)/256, 256>>>(conv_w, pcw, EMB*EMB);
    }

    // ---- patch embedding ----
    im2col_kernel<<<(PROWS*EMB + 255)/256, 256>>>(x, pimh);
    gemm_hmma<<<dim3(EMB/BN, PROWS/BM, 1), 256, GEMM_SMEM>>>(
        pimh, pcw, conv_b, pt, nullptr, PROWS, EMB, EMB, EMB, 0);
    embed_kernel<<<(ROWS*EMB + 255)/256, 256>>>(pt, cls_tok, pos_emb, ph, phh);

    const int mtiles = (ROWS + BM - 1) / BM;     // 50
    const dim3 gQKV(QS/BN, mtiles, 1);           // 18 x 50
    const dim3 gEs(EMB/BN, mtiles, NSPLIT);      // 6 x 50 x 2 (split-K2)
    const dim3 gF1(FF/BN,  mtiles, 1);           // 24 x 50
    const dim3 gAT(4, BATCH*NHEAD);

    for (int l = 0; l < DEPTH; l++) {
        size_t base = (size_t)l * LSTRIDE;
        const __half* qkvw = pw + base + OFF_Q;   // [2304, 768]
        const __half* ow   = pw + base + OFF_O;
        const __half* w1w  = pw + base + OFF_W1;
        const __half* w2w  = pw + base + OFF_W2;
        const float* bol= bo + (size_t)l*EMB;
        const float* g1 = ln1_g + (size_t)l*EMB;
        const float* be1= ln1_b + (size_t)l*EMB;
        const float* bb1= b1 + (size_t)l*FF;
        const float* bb2= b2 + (size_t)l*EMB;
        const float* g2 = ln2_g + (size_t)l*EMB;
        const float* be2= ln2_b + (size_t)l*EMB;

        // QKV emits fp16 directly
        gemm_hmma<<<gQKV, 256, GEMM_SMEM>>>(phh, qkvw, nullptr,
                                            nullptr, pqkv, ROWS, QS, EMB, EMB, 0);

        attn_tc<<<gAT, 256, ATT_SMEM>>>(pqkv, pth);

        // O-proj split-K2: partials in pt/pt2; bias folded into add_ln
        gemm_hmma<<<gEs, 256, GEMM_SMEM>>>(pth, ow, nullptr,
                                           pt, nullptr, ROWS, EMB,
                                           EMB / NSPLIT, EMB, 0);
        add_ln<<<ROWS, 192>>>(pt, pt2, bol, ph, g1, be1, px, pxh);

        gemm_hmma<<<gF1, 256, GEMM_SMEM>>>(pxh, w1w, bb1,
                                           nullptr, pfh, ROWS, FF, EMB, EMB, 1);
        // FF2 split-K2
        gemm_hmma<<<gEs, 256, GEMM_SMEM>>>(pfh, w2w, nullptr,
                                           pt, nullptr, ROWS, EMB,
                                           FF / NSPLIT, FF, 0);
        add_ln<<<ROWS, 192>>>(pt, pt2, bb2, px, g2, be2, ph, phh);
    }

    cls_ln<<<BATCH, 256>>>(ph, head_g, head_b, pcls);
    head_gemm<<<(BATCH*NCLS + 255)/256, 256>>>(pcls, head_W, head_bias, out);
}

// round 16
// speedup vs baseline: 1.1062x; 1.0176x over previous
#include <cuda_runtime.h>
#include <cuda_fp16.h>
#include <cstdint>
#include <cstddef>

// ---------------- Problem constants ----------------
#define IMG   224
#define PATCH 16
#define EMB   768
#define DEPTH 12
#define NHEAD 12
#define HD    64
#define FF    3072
#define NCLS  1000
#define BATCH 32
#define NP    196
#define NTOK  197
#define ROWS  (BATCH * NTOK) // 6304
#define PROWS (BATCH * NP)   // 6272
#define EPS   1e-5f
#define QS    2304           // fused qkv row stride
#define NSPLIT 2             // split-K factor for O-proj / FF2

// weight layout (per layer, element offsets). Q,K,V contiguous -> fused QKV.
#define OFF_Q   0
#define OFF_K   589824
#define OFF_V   1179648
#define OFF_O   1769472
#define OFF_W1  2359296
#define OFF_W2  4718592
#define LSTRIDE 7077888
#define WTOTAL  (LSTRIDE * DEPTH)

// ---------------- Scratch ----------------
__device__ float g_h  [ROWS * EMB];             // trunk fp32
__device__ float g_x  [ROWS * EMB];             // post-LN1 fp32
__device__ float g_t  [NSPLIT * ROWS * EMB];    // split-K partial buffers
__device__ float g_cls[BATCH * EMB];
__device__ __half g_qkv[ROWS * QS];             // fused qkv fp16
__device__ __half g_hh [ROWS * EMB];
__device__ __half g_xh [ROWS * EMB];
__device__ __half g_th [ROWS * EMB];
__device__ __half g_fh [ROWS * FF];
__device__ __half g_imh[PROWS * EMB];
__device__ __half g_w  [WTOTAL];                // weights fp16, [N,K]
__device__ __half g_cw [EMB * EMB];

// ---------------- helpers ----------------
__device__ __forceinline__ uint32_t smem_u32(const void* p) {
    uint32_t a;
    asm("{ .reg .u64 t; cvta.to.shared.u64 t, %1; cvt.u32.u64 %0, t; }"
        : "=r"(a) : "l"(p));
    return a;
}
__device__ __forceinline__ void ldm_x4(uint32_t (&r)[4], uint32_t addr) {
    asm volatile("ldmatrix.sync.aligned.m8n8.x4.shared.b16 {%0,%1,%2,%3}, [%4];"
                 : "=r"(r[0]), "=r"(r[1]), "=r"(r[2]), "=r"(r[3]) : "r"(addr));
}
__device__ __forceinline__ void ldm_x4_trans(uint32_t (&r)[4], uint32_t addr) {
    asm volatile("ldmatrix.sync.aligned.m8n8.x4.trans.shared.b16 {%0,%1,%2,%3}, [%4];"
                 : "=r"(r[0]), "=r"(r[1]), "=r"(r[2]), "=r"(r[3]) : "r"(addr));
}
__device__ __forceinline__ void mma_f16(float (&d)[4], const uint32_t (&a)[4],
                                        const uint32_t (&b)[2]) {
    asm volatile("mma.sync.aligned.m16n8k16.row.col.f32.f16.f16.f32 "
                 "{%0,%1,%2,%3}, {%4,%5,%6,%7}, {%8,%9}, {%0,%1,%2,%3};"
                 : "+f"(d[0]), "+f"(d[1]), "+f"(d[2]), "+f"(d[3])
                 : "r"(a[0]), "r"(a[1]), "r"(a[2]), "r"(a[3]),
                   "r"(b[0]), "r"(b[1]));
}
__device__ __forceinline__ uint32_t pack_h2(float x, float y) {
    __half2 h = __floats2half2_rn(x, y);
    return *reinterpret_cast<uint32_t*>(&h);
}

// ------- weight prep: transpose [K,N] -> [N,K], fp16 (multi-source batch) ---
__global__ void transpose_half_batch4(const float* __restrict__ W0,
                                      const float* __restrict__ W1,
                                      const float* __restrict__ W2,
                                      const float* __restrict__ W3,
                                      __half* __restrict__ out,
                                      size_t o_src_stride)   // per-source out off
{
    __shared__ float t[32][33];
    const int z     = blockIdx.z;
    const int layer = z % DEPTH;
    const int which = z / DEPTH;
    const float* W  = (which == 0) ? W0 : (which == 1) ? W1
                    : (which == 2) ? W2 : W3;
    W   += (size_t)layer * EMB * EMB;
    out += (size_t)layer * LSTRIDE + (size_t)which * o_src_stride;
    int nb = blockIdx.x * 32, kb = blockIdx.y * 32;
    int tx = threadIdx.x, ty = threadIdx.y;
    #pragma unroll
    for (int j = ty; j < 32; j += 8)
        t[j][tx] = W[(size_t)(kb + j) * EMB + nb + tx];
    __syncthreads();
    #pragma unroll
    for (int j = ty; j < 32; j += 8)
        out[(size_t)(nb + j) * EMB + kb + tx] = __float2half_rn(t[tx][j]);
}

__global__ void transpose_half_batch(const float* __restrict__ W,
                                     __half* __restrict__ out,
                                     int K, int N,
                                     size_t w_lstride, size_t o_lstride)
{
    __shared__ float t[32][33];
    const int layer = blockIdx.z;
    W   += (size_t)layer * w_lstride;
    out += (size_t)layer * o_lstride;
    int nb = blockIdx.x * 32, kb = blockIdx.y * 32;
    int tx = threadIdx.x, ty = threadIdx.y;
    #pragma unroll
    for (int j = ty; j < 32; j += 8)
        t[j][tx] = W[(size_t)(kb + j) * N + nb + tx];
    __syncthreads();
    #pragma unroll
    for (int j = ty; j < 32; j += 8)
        out[(size_t)(nb + j) * K + kb + tx] = __float2half_rn(t[tx][j]);
}

__global__ void tohalf_only(const float* __restrict__ W,
                            __half* __restrict__ out, int n)
{
    int i = blockIdx.x * blockDim.x + threadIdx.x;
    if (i < n) out[i] = __float2half_rn(W[i]);
}

// ---------------- pipelined HMMA GEMM (single-pass fp16, fp32 accum) --------
#define BM 128
#define BN 128
#define BK 64
#define ROWB 144                    // 64*2 + 16 pad bytes per smem row
#define ARR_B (128 * ROWB)          // 18432
#define STAGE_B (2 * ARR_B)         // 36864
#define GEMM_SMEM (3 * STAGE_B)     // 110592 (3-stage)

__global__ __launch_bounds__(256, 2)
void gemm_hmma(const __half* __restrict__ A,
               const __half* __restrict__ B,
               const float* __restrict__ bias,
               float* __restrict__ Cf,
               __half* __restrict__ Ch,
               int M, int N, int Kspan, int ldK, int do_relu)
{
    extern __shared__ __align__(16) unsigned char dsm[];
    const uint32_t smb = smem_u32(dsm);
    const int tid  = threadIdx.x;
    const int lane = tid & 31;
    const int wid  = tid >> 5;
    const int wm   = wid & 1;
    const int wn   = wid >> 1;
    const int row0 = blockIdx.y * BM;
    const int col0 = blockIdx.x * BN;
    const int kz   = blockIdx.z;

    const __half* Ab = A + (size_t)kz * Kspan;
    const __half* Bb = B + (size_t)kz * Kspan;
    if (Cf) Cf += (size_t)kz * M * N;

    float acc[4][4][4] = {};

    auto load_stage = [&](int s, int kt) {
        #pragma unroll
        for (int l = 0; l < 8; l++) {
            int idx = tid + l * 256;
            int arr = idx >> 10;
            int w   = idx & 1023;
            int r   = w >> 3;
            int q   = w & 7;
            int row = (arr ? col0 : row0) + r;
            const __half* src = (arr ? Bb : Ab) + (size_t)row * ldK + kt + q * 8;
            int bytes = (!arr && row >= M) ? 0 : 16;
            uint32_t dst = smb + (uint32_t)s * STAGE_B + (uint32_t)arr * ARR_B
                         + (uint32_t)r * ROWB + (uint32_t)q * 16u;
            asm volatile("cp.async.cg.shared.global [%0], [%1], 16, %2;"
                         :: "r"(dst), "l"(src), "r"(bytes) : "memory");
        }
        asm volatile("cp.async.commit_group;" ::: "memory");
    };

    auto compute_stage = [&](int s) {
        const uint32_t uA = smb + (uint32_t)s * STAGE_B;
        const uint32_t uB = uA + ARR_B;
        #pragma unroll
        for (int kk = 0; kk < 4; kk++) {
            const uint32_t kcb = (kk * 16 + ((lane >> 4) << 3)) * 2;
            uint32_t af[4][4];
            uint32_t bf[4][2];
            #pragma unroll
            for (int mi = 0; mi < 4; mi++) {
                uint32_t off = (uint32_t)(wm * 64 + mi * 16 + (lane & 15)) * ROWB + kcb;
                ldm_x4(af[mi], uA + off);
            }
            #pragma unroll
            for (int g = 0; g < 2; g++) {
                uint32_t off = (uint32_t)(wn * 32 + g * 16 + (lane & 15)) * ROWB + kcb;
                uint32_t tb[4];
                ldm_x4(tb, uB + off);
                bf[g*2+0][0] = tb[0]; bf[g*2+0][1] = tb[2];
                bf[g*2+1][0] = tb[1]; bf[g*2+1][1] = tb[3];
            }
            #pragma unroll
            for (int mi = 0; mi < 4; mi++)
                #pragma unroll
                for (int n = 0; n < 4; n++)
                    mma_f16(acc[mi][n], af[mi], bf[n]);
        }
    };

    const int nk = Kspan / BK;          // >= 6 for all launched shapes
    load_stage(0, 0);
    load_stage(1, BK);
    for (int i = 0; i < nk; i++) {
        if (i == nk - 1)
            asm volatile("cp.async.wait_group 0;" ::: "memory");
        else
            asm volatile("cp.async.wait_group 1;" ::: "memory");
        __syncthreads();    // group i visible; all threads done computing stage (i-1)
        if (i + 2 < nk)
            load_stage((i + 2) % 3, (i + 2) * BK);
        compute_stage(i % 3);
    }

    // ---- epilogue ----
    const bool hb = (bias != nullptr);
    #pragma unroll
    for (int mi = 0; mi < 4; mi++) {
        #pragma unroll
        for (int n = 0; n < 4; n++) {
            int gc = col0 + wn * 32 + n * 8 + (lane & 3) * 2;
            float bx = 0.f, by = 0.f;
            if (hb) { bx = bias[gc]; by = bias[gc + 1]; }
            #pragma unroll
            for (int h = 0; h < 2; h++) {
                int gr = row0 + wm * 64 + mi * 16 + (lane >> 2) + h * 8;
                if (gr >= M) continue;
                float ox = acc[mi][n][h * 2 + 0] + bx;
                float oy = acc[mi][n][h * 2 + 1] + by;
                if (do_relu) { ox = fmaxf(ox, 0.f); oy = fmaxf(oy, 0.f); }
                size_t o = (size_t)gr * N + gc;
                if (Cf)
                    *reinterpret_cast<float2*>(&Cf[o]) = make_float2(ox, oy);
                if (Ch)
                    *reinterpret_cast<uint32_t*>(&Ch[o]) = pack_h2(ox, oy);
            }
        }
    }
}

// ---------------- im2col (emits fp16) ---------------------------------------
__global__ void im2col_kernel(const float* __restrict__ x,
                              __half* __restrict__ ho)
{
    int idx = blockIdx.x * blockDim.x + threadIdx.x;
    if (idx >= PROWS * EMB) return;
    int row = idx / EMB;
    int k   = idx % EMB;
    int b   = row / NP;
    int p   = row % NP;
    int py  = p / 14, px = p % 14;
    int c   = k / 256;
    int r2  = k % 256;
    int ph  = r2 / PATCH, pw = r2 % PATCH;
    float v = x[(((size_t)b * 3 + c) * IMG + (py * PATCH + ph)) * IMG
                + (px * PATCH + pw)];
    ho[idx] = __float2half_rn(v);
}

__global__ void embed_kernel(const float* __restrict__ patch,
                             const float* __restrict__ cls_tok,
                             const float* __restrict__ pos,
                             float* __restrict__ h,
                             __half* __restrict__ hh)
{
    int idx = blockIdx.x * blockDim.x + threadIdx.x;
    if (idx >= ROWS * EMB) return;
    int row = idx / EMB;
    int e   = idx % EMB;
    int b   = row / NTOK;
    int n   = row % NTOK;
    float base = (n == 0) ? cls_tok[e]
                          : patch[((size_t)b * NP + (n - 1)) * EMB + e];
    float v = base + pos[n * EMB + e];
    h[idx]  = v;
    hh[idx] = __float2half_rn(v);
}

// ---------------- tensor-core fused attention --------------------------------
#define AT_QSTR 72
#define AT_KSTR 72
#define AT_ASTR 232
#define AT_Q_OFF   0
#define AT_KV_OFF  9216          // 64*72*2
#define AT_A_OFF   41472         // 9216 + 224*72*2
#define AT_RED_OFF 71168         // 41472 + 64*232*2
#define ATT_SMEM   72192         // + 256*4

__global__ __launch_bounds__(256, 2)
void attn_tc(const __half* __restrict__ qkv, __half* __restrict__ th)
{
    extern __shared__ __align__(16) char smc[];
    __half* Qh = reinterpret_cast<__half*>(smc + AT_Q_OFF);
    __half* Kh = reinterpret_cast<__half*>(smc + AT_KV_OFF);   // K, then V
    __half* Ah = reinterpret_cast<__half*>(smc + AT_A_OFF);
    float* redM = reinterpret_cast<float*>(smc + AT_RED_OFF);  // [2][64]
    float* redS = redM + 128;                                  // [2][64]

    const int bh = blockIdx.y;
    const int b  = bh / NHEAD;
    const int hh = bh % NHEAD;
    const int q0 = blockIdx.x * 64;
    const float scale = 0.036084391824f;   // 1/sqrt(768)

    const int tid  = threadIdx.x;
    const int lane = tid & 31;
    const int wid  = tid >> 5;
    const int wm   = wid & 3;
    const int wn   = wid >> 2;

    const __half* Qb = qkv + (size_t)b * NTOK * QS + hh * HD;
    const __half* Kb = Qb + 768;
    const __half* Vb = Qb + 1536;

    const uint32_t uQ = smem_u32(Qh);
    const uint32_t uK = smem_u32(Kh);
    const uint32_t uA = smem_u32(Ah);

    // ---- load Q (64 x 64) ----
    #pragma unroll
    for (int l = 0; l < 4; l++) {
        int idx = tid + l * 256;
        int r   = idx >> 4;
        int c4  = (idx & 15) << 2;
        uint2 v = make_uint2(0u, 0u);
        if (q0 + r < NTOK)
            v = *reinterpret_cast<const uint2*>(&Qb[(size_t)(q0 + r) * QS + c4]);
        *reinterpret_cast<uint32_t*>(&Qh[r * AT_QSTR + c4])     = v.x;
        *reinterpret_cast<uint32_t*>(&Qh[r * AT_QSTR + c4 + 2]) = v.y;
    }
    // ---- load K (224 x 64, zero-padded past NTOK) ----
    #pragma unroll
    for (int l = 0; l < 14; l++) {
        int idx = tid + l * 256;
        int r   = idx >> 4;
        int c4  = (idx & 15) << 2;
        uint2 v = make_uint2(0u, 0u);
        if (r < NTOK)
            v = *reinterpret_cast<const uint2*>(&Kb[(size_t)r * QS + c4]);
        *reinterpret_cast<uint32_t*>(&Kh[r * AT_KSTR + c4])     = v.x;
        *reinterpret_cast<uint32_t*>(&Kh[r * AT_KSTR + c4 + 2]) = v.y;
    }
    __syncthreads();

    // ---- phase 1: scores via mma ----
    float acc[14][4];
    #pragma unroll
    for (int t = 0; t < 14; t++)
        #pragma unroll
        for (int j = 0; j < 4; j++) acc[t][j] = 0.f;

    #pragma unroll
    for (int ks = 0; ks < 4; ks++) {
        const uint32_t kcb = (ks * 16 + ((lane >> 4) << 3)) * 2;
        uint32_t af[4];
        ldm_x4(af, uQ + (uint32_t)(wm * 16 + (lane & 15)) * (AT_QSTR * 2) + kcb);
        #pragma unroll
        for (int g = 0; g < 7; g++) {
            uint32_t tb[4];
            ldm_x4(tb, uK + (uint32_t)(wn * 112 + g * 16 + (lane & 15)) * (AT_KSTR * 2) + kcb);
            uint32_t b0[2] = {tb[0], tb[2]};
            uint32_t b1[2] = {tb[1], tb[3]};
            mma_f16(acc[g * 2 + 0], af, b0);
            mma_f16(acc[g * 2 + 1], af, b1);
        }
    }

    // ---- register softmax ----
    const int row0 = wm * 16 + (lane >> 2);
    const int cb   = wn * 112 + (lane & 3) * 2;
    #pragma unroll
    for (int t = 0; t < 14; t++) {
        #pragma unroll
        for (int j = 0; j < 4; j++) {
            int gc = cb + t * 8 + (j & 1);
            float v = acc[t][j] * scale;
            acc[t][j] = (gc < NTOK) ? v : -1e30f;
        }
    }
    float m0 = -1e30f, m1 = -1e30f;
    #pragma unroll
    for (int t = 0; t < 14; t++) {
        m0 = fmaxf(m0, fmaxf(acc[t][0], acc[t][1]));
        m1 = fmaxf(m1, fmaxf(acc[t][2], acc[t][3]));
    }
    m0 = fmaxf(m0, __shfl_xor_sync(0xffffffffu, m0, 1));
    m0 = fmaxf(m0, __shfl_xor_sync(0xffffffffu, m0, 2));
    m1 = fmaxf(m1, __shfl_xor_sync(0xffffffffu, m1, 1));
    m1 = fmaxf(m1, __shfl_xor_sync(0xffffffffu, m1, 2));
    if ((lane & 3) == 0) {
        redM[wn * 64 + row0]     = m0;
        redM[wn * 64 + row0 + 8] = m1;
    }
    __syncthreads();
    const float M0 = fmaxf(redM[row0],     redM[64 + row0]);
    const float M1 = fmaxf(redM[row0 + 8], redM[64 + row0 + 8]);

    float s0 = 0.f, s1 = 0.f;
    #pragma unroll
    for (int t = 0; t < 14; t++) {
        acc[t][0] = expf(acc[t][0] - M0);
        acc[t][1] = expf(acc[t][1] - M0);
        acc[t][2] = expf(acc[t][2] - M1);
        acc[t][3] = expf(acc[t][3] - M1);
        s0 += acc[t][0] + acc[t][1];
        s1 += acc[t][2] + acc[t][3];
    }
    s0 += __shfl_xor_sync(0xffffffffu, s0, 1);
    s0 += __shfl_xor_sync(0xffffffffu, s0, 2);
    s1 += __shfl_xor_sync(0xffffffffu, s1, 1);
    s1 += __shfl_xor_sync(0xffffffffu, s1, 2);
    if ((lane & 3) == 0) {
        redS[wn * 64 + row0]     = s0;
        redS[wn * 64 + row0 + 8] = s1;
    }
    __syncthreads();
    const float inv0 = 1.f / (redS[row0]     + redS[64 + row0]);
    const float inv1 = 1.f / (redS[row0 + 8] + redS[64 + row0 + 8]);

    // write fp16 attn weights (cols 0..223; invalid -> 0)
    #pragma unroll
    for (int t = 0; t < 14; t++) {
        int gc = wn * 112 + t * 8 + (lane & 3) * 2;
        *reinterpret_cast<uint32_t*>(&Ah[row0 * AT_ASTR + gc]) =
            pack_h2(acc[t][0] * inv0, acc[t][1] * inv0);
        *reinterpret_cast<uint32_t*>(&Ah[(row0 + 8) * AT_ASTR + gc]) =
            pack_h2(acc[t][2] * inv1, acc[t][3] * inv1);
    }
    __syncthreads();   // attn written; reuse Kh for V

    // ---- load V natural [kv][d] ----
    #pragma unroll
    for (int l = 0; l < 14; l++) {
        int idx = tid + l * 256;
        int r   = idx >> 4;
        int c4  = (idx & 15) << 2;
        uint2 v = make_uint2(0u, 0u);
        if (r < NTOK)
            v = *reinterpret_cast<const uint2*>(&Vb[(size_t)r * QS + c4]);
        *reinterpret_cast<uint32_t*>(&Kh[r * AT_KSTR + c4])     = v.x;
        *reinterpret_cast<uint32_t*>(&Kh[r * AT_KSTR + c4 + 2]) = v.y;
    }
    __syncthreads();

    // ---- phase 3: out = attn @ V (B-frags via ldmatrix.trans) ----
    float oac[4][4];
    #pragma unroll
    for (int t = 0; t < 4; t++)
        #pragma unroll
        for (int j = 0; j < 4; j++) oac[t][j] = 0.f;

    #pragma unroll
    for (int ks = 0; ks < 14; ks++) {
        const uint32_t kcb = (ks * 16 + ((lane >> 4) << 3)) * 2;
        uint32_t af[4];
        ldm_x4(af, uA + (uint32_t)(wm * 16 + (lane & 15)) * (AT_ASTR * 2) + kcb);
        #pragma unroll
        for (int g = 0; g < 2; g++) {
            uint32_t tb[4];
            uint32_t vaddr = uK
                + (uint32_t)(ks * 16 + (lane & 15)) * (AT_KSTR * 2)
                + (uint32_t)(wn * 32 + g * 16 + ((lane >> 4) << 3)) * 2;
            ldm_x4_trans(tb, vaddr);
            uint32_t b0[2] = {tb[0], tb[1]};
            uint32_t b1[2] = {tb[2], tb[3]};
            mma_f16(oac[g * 2 + 0], af, b0);
            mma_f16(oac[g * 2 + 1], af, b1);
        }
    }

    // ---- epilogue ----
    #pragma unroll
    for (int t = 0; t < 4; t++) {
        int gd = wn * 32 + t * 8 + (lane & 3) * 2;
        #pragma unroll
        for (int h = 0; h < 2; h++) {
            int qr = q0 + wm * 16 + (lane >> 2) + h * 8;
            if (qr >= NTOK) continue;
            size_t o = ((size_t)b * NTOK + qr) * EMB + hh * HD + gd;
            *reinterpret_cast<uint32_t*>(&th[o]) =
                pack_h2(oac[t][h * 2 + 0], oac[t][h * 2 + 1]);
        }
    }
}

// ------ fused split-K2 reduce + bias + residual + LN + fp16 emit ------------
__global__ __launch_bounds__(256)
void add_ln(const float* __restrict__ a0, const float* __restrict__ a1,
            const float* __restrict__ abias,
            const float* __restrict__ b,
            const float* __restrict__ g, const float* __restrict__ be,
            float* __restrict__ out, __half* __restrict__ oh)
{
    const int r   = blockIdx.x;
    const int tid = threadIdx.x;
    float v[3];
    float s = 0.f, q = 0.f;
    #pragma unroll
    for (int t = 0; t < 3; t++) {
        int c = tid + t * 256;
        size_t idx = (size_t)r * EMB + c;
        v[t] = a0[idx] + a1[idx] + abias[c] + b[idx];
        s += v[t];
        q += v[t] * v[t];
    }
    #pragma unroll
    for (int o = 16; o; o >>= 1) {
        s += __shfl_xor_sync(0xffffffffu, s, o);
        q += __shfl_xor_sync(0xffffffffu, q, o);
    }
    __shared__ float red[2][8];
    int w = tid >> 5, lane = tid & 31;
    if (lane == 0) { red[0][w] = s; red[1][w] = q; }
    __syncthreads();
    s = 0.f; q = 0.f;
    #pragma unroll
    for (int i = 0; i < 8; i++) { s += red[0][i]; q += red[1][i]; }
    float mean = s * (1.f / EMB);
    float var  = q * (1.f / EMB) - mean * mean;
    float rstd = rsqrtf(var + EPS);
    #pragma unroll
    for (int t = 0; t < 3; t++) {
        int c = tid + t * 256;
        float o = (v[t] - mean) * rstd * g[c] + be[c];
        size_t idx = (size_t)r * EMB + c;
        out[idx] = o;
        oh[idx]  = __float2half_rn(o);
    }
}

__global__ __launch_bounds__(256)
void cls_ln(const float* __restrict__ h, const float* __restrict__ g,
            const float* __restrict__ be, float* __restrict__ out)
{
    const int b   = blockIdx.x;
    const int tid = threadIdx.x;
    const float* row = h + (size_t)b * NTOK * EMB;
    float v[3];
    float s = 0.f, q = 0.f;
    #pragma unroll
    for (int t = 0; t < 3; t++) {
        int c = tid + t * 256;
        v[t] = row[c];
        s += v[t];
        q += v[t] * v[t];
    }
    #pragma unroll
    for (int o = 16; o; o >>= 1) {
        s += __shfl_xor_sync(0xffffffffu, s, o);
        q += __shfl_xor_sync(0xffffffffu, q, o);
    }
    __shared__ float red[2][8];
    int w = tid >> 5, lane = tid & 31;
    if (lane == 0) { red[0][w] = s; red[1][w] = q; }
    __syncthreads();
    s = 0.f; q = 0.f;
    #pragma unroll
    for (int i = 0; i < 8; i++) { s += red[0][i]; q += red[1][i]; }
    float mean = s * (1.f / EMB);
    float var  = q * (1.f / EMB) - mean * mean;
    float rstd = rsqrtf(var + EPS);
    #pragma unroll
    for (int t = 0; t < 3; t++) {
        int c = tid + t * 256;
        out[(size_t)b * EMB + c] = (v[t] - mean) * rstd * g[c] + be[c];
    }
}

// ---------------- classifier head -------------------------------------------
__global__ __launch_bounds__(256)
void head_gemm(const float* __restrict__ cls, const float* __restrict__ W,
               const float* __restrict__ bias, float* __restrict__ out)
{
    int idx = blockIdx.x * blockDim.x + threadIdx.x;
    if (idx >= BATCH * NCLS) return;
    int b = idx / NCLS;
    int n = idx % NCLS;
    float s = bias[n];
    const float* c = cls + (size_t)b * EMB;
    for (int k = 0; k < EMB; k++)
        s = fmaf(c[k], W[(size_t)k * NCLS + n], s);
    out[idx] = s;
}

// ---------------- driver -----------------------------------------------------
extern "C" void kernel_launch(void* const* d_in, const int* in_sizes, int n_in,
                              void* d_out, int out_size)
{
    const float* x        = (const float*)d_in[0];
    const float* conv_w   = (const float*)d_in[1];
    const float* conv_b   = (const float*)d_in[2];
    const float* cls_tok  = (const float*)d_in[3];
    const float* pos_emb  = (const float*)d_in[4];
    const float* Wq       = (const float*)d_in[5];
    const float* Wk       = (const float*)d_in[6];
    const float* Wv       = (const float*)d_in[7];
    const float* Wo       = (const float*)d_in[8];
    const float* bo       = (const float*)d_in[9];
    const float* ln1_g    = (const float*)d_in[10];
    const float* ln1_b    = (const float*)d_in[11];
    const float* W1       = (const float*)d_in[12];
    const float* b1       = (const float*)d_in[13];
    const float* W2       = (const float*)d_in[14];
    const float* b2       = (const float*)d_in[15];
    const float* ln2_g    = (const float*)d_in[16];
    const float* ln2_b    = (const float*)d_in[17];
    const float* head_g   = (const float*)d_in[18];
    const float* head_b   = (const float*)d_in[19];
    const float* head_W   = (const float*)d_in[20];
    const float* head_bias= (const float*)d_in[21];
    float* out = (float*)d_out;

    float *ph, *px, *pt, *pcls;
    __half *pqkv, *phh, *pxh, *pth, *pfh, *pimh, *pw, *pcw;
    cudaGetSymbolAddress((void**)&ph,   g_h);
    cudaGetSymbolAddress((void**)&px,   g_x);
    cudaGetSymbolAddress((void**)&pt,   g_t);
    cudaGetSymbolAddress((void**)&pcls, g_cls);
    cudaGetSymbolAddress((void**)&pqkv, g_qkv);
    cudaGetSymbolAddress((void**)&phh,  g_hh);
    cudaGetSymbolAddress((void**)&pxh,  g_xh);
    cudaGetSymbolAddress((void**)&pth,  g_th);
    cudaGetSymbolAddress((void**)&pfh,  g_fh);
    cudaGetSymbolAddress((void**)&pimh, g_imh);
    cudaGetSymbolAddress((void**)&pw,   g_w);
    cudaGetSymbolAddress((void**)&pcw,  g_cw);
    float* pt2 = pt + (size_t)ROWS * EMB;

    cudaFuncSetAttribute(gemm_hmma, cudaFuncAttributeMaxDynamicSharedMemorySize,
                         GEMM_SMEM);
    cudaFuncSetAttribute(attn_tc, cudaFuncAttributeMaxDynamicSharedMemorySize,
                         ATT_SMEM);

    // ---- weight prep: batched transpose to [N,K] fp16 ----
    {
        dim3 blk(32, 8);
        // Wq/Wk/Wv/Wo in ONE launch (z selects source+layer)
        dim3 g4(EMB/32, EMB/32, 4 * DEPTH);
        transpose_half_batch4<<<g4, blk>>>(Wq, Wk, Wv, Wo, pw,
                                           (size_t)EMB * EMB);
        dim3 g1(FF/32, EMB/32, DEPTH);
        transpose_half_batch<<<g1, blk>>>(W1, pw + OFF_W1, EMB, FF,
                                          (size_t)EMB*FF, LSTRIDE);
        dim3 g2(EMB/32, FF/32, DEPTH);
        transpose_half_batch<<<g2, blk>>>(W2, pw + OFF_W2, FF, EMB,
                                          (size_t)FF*EMB, LSTRIDE);
        tohalf_only<<<(EMB*EMB + 255)/256, 256>>>(conv_w, pcw, EMB*EMB);
    }

    // ---- patch embedding ----
    im2col_kernel<<<(PROWS*EMB + 255)/256, 256>>>(x, pimh);
    gemm_hmma<<<dim3(EMB/BN, PROWS/BM, 1), 256, GEMM_SMEM>>>(
        pimh, pcw, conv_b, pt, nullptr, PROWS, EMB, EMB, EMB, 0);
    embed_kernel<<<(ROWS*EMB + 255)/256, 256>>>(pt, cls_tok, pos_emb, ph, phh);

    const int mtiles = (ROWS + BM - 1) / BM;     // 50
    const dim3 gQKV(QS/BN, mtiles, 1);           // 18 x 50
    const dim3 gEs(EMB/BN, mtiles, NSPLIT);      // 6 x 50 x 2 (split-K2)
    const dim3 gF1(FF/BN,  mtiles, 1);           // 24 x 50
    const dim3 gAT(4, BATCH*NHEAD);

    for (int l = 0; l < DEPTH; l++) {
        size_t base = (size_t)l * LSTRIDE;
        const __half* qkvw = pw + base + OFF_Q;   // [2304, 768]
        const __half* ow   = pw + base + OFF_O;
        const __half* w1w  = pw + base + OFF_W1;
        const __half* w2w  = pw + base + OFF_W2;
        const float* bol= bo + (size_t)l*EMB;
        const float* g1 = ln1_g + (size_t)l*EMB;
        const float* be1= ln1_b + (size_t)l*EMB;
        const float* bb1= b1 + (size_t)l*FF;
        const float* bb2= b2 + (size_t)l*EMB;
        const float* g2 = ln2_g + (size_t)l*EMB;
        const float* be2= ln2_b + (size_t)l*EMB;

        // QKV emits fp16 directly
        gemm_hmma<<<gQKV, 256, GEMM_SMEM>>>(phh, qkvw, nullptr,
                                            nullptr, pqkv, ROWS, QS, EMB, EMB, 0);

        attn_tc<<<gAT, 256, ATT_SMEM>>>(pqkv, pth);

        // O-proj split-K2: partials in pt/pt2; bias folded into add_ln
        gemm_hmma<<<gEs, 256, GEMM_SMEM>>>(pth, ow, nullptr,
                                           pt, nullptr, ROWS, EMB,
                                           EMB / NSPLIT, EMB, 0);
        add_ln<<<ROWS, 256>>>(pt, pt2, bol, ph, g1, be1, px, pxh);

        gemm_hmma<<<gF1, 256, GEMM_SMEM>>>(pxh, w1w, bb1,
                                           nullptr, pfh, ROWS, FF, EMB, EMB, 1);
        // FF2 split-K2
        gemm_hmma<<<gEs, 256, GEMM_SMEM>>>(pfh, w2w, nullptr,
                                           pt, nullptr, ROWS, EMB,
                                           FF / NSPLIT, FF, 0);
        add_ln<<<ROWS, 256>>>(pt, pt2, bb2, px, g2, be2, ph, phh);
    }

    cls_ln<<<BATCH, 256>>>(ph, head_g, head_b, pcls);
    head_gemm<<<(BATCH*NCLS + 255)/256, 256>>>(pcls, head_W, head_bias, out);
}